// round 7
// baseline (speedup 1.0000x reference)
#include <cuda_runtime.h>

#define BATCH 2048
#define NPTS  4095
#define TPB   512
#define EPT   8            // TPB*EPT = 4096
#define NWARP (TPB/32)     // 16
#define PADN  4096

__device__ float g_partial[BATCH];
__device__ int   g_count = 0;

// dynamic smem: ssx[4096] ssy[4096] ssz[4096] = 48 KB
#define SMEM_BYTES (3 * PADN * 4)

extern __shared__ __align__(16) float sstage[];

__global__ void __launch_bounds__(TPB, 3)
mpd_fused_kernel(const float* __restrict__ o3,
                 const float* __restrict__ s3,
                 const float* __restrict__ o2,
                 const float* __restrict__ s2,
                 const float* __restrict__ df,
                 float* __restrict__ out)
{
    float* ssx = sstage;
    float* ssy = sstage + PADN;
    float* ssz = sstage + 2 * PADN;
    __shared__ float wtot[3][NWARP];
    __shared__ float red[NWARP];
    __shared__ int   is_last;

    const int b = blockIdx.x;
    const int t = threadIdx.x;
    const unsigned lane = t & 31u;
    const unsigned warp = t >> 5;

    const float* __restrict__ s3b = s3 + (size_t)b * (3 * NPTS);
    const float* __restrict__ s2b = s2 + (size_t)b * (3 * NPTS);
    const float* __restrict__ dfb = df + (size_t)b * (2 * NPTS);

    const float dx = o3[b * 3 + 0] - o2[b * 3 + 0];
    const float dy = o3[b * 3 + 1] - o2[b * 3 + 1];
    const float dz = o3[b * 3 + 2] - o2[b * 3 + 2];

    // ---- Phase A: one long coalesced load+trig burst, staged to smem ----
    #pragma unroll
    for (int k = 0; k < EPT; k++) {
        const int i = t + k * TPB;            // lane stride 4B, coalesced
        float vx = 0.f, vy = 0.f, vz = 0.f;
        if (i < NPTS) {                        // only i==4095 fails
            float r3  = s3b[i];
            float th3 = s3b[i + NPTS];
            float ph3 = s3b[i + 2 * NPTS];
            float r2  = s2b[i];
            float th2 = s2b[i + NPTS];
            float ph2 = s2b[i + 2 * NPTS];
            float dt  = dfb[i];
            float dp  = dfb[i + NPTS];

            float st, ct, sp, cp;
            __sincosf(th3 + dt, &st, &ct);
            __sincosf(ph3 + dp, &sp, &cp);
            float rst = r3 * st;
            vx = rst * cp; vy = rst * sp; vz = r3 * ct;
            __sincosf(th2, &st, &ct);
            __sincosf(ph2, &sp, &cp);
            rst = r2 * st;
            vx -= rst * cp; vy -= rst * sp; vz -= r2 * ct;
        }
        ssx[i] = vx; ssy[i] = vy; ssz[i] = vz;   // stride-1, conflict-free
    }
    __syncthreads();                              // barrier #1

    // ---- Phase B1: sum-only sweep (blocked LDS.128) -> thread totals ----
    const int base = t * EPT;                     // 32B aligned
    float tx, ty, tz;
    {
        float4 A = *reinterpret_cast<const float4*>(ssx + base);
        float4 B = *reinterpret_cast<const float4*>(ssx + base + 4);
        tx = (A.x + A.y) + (A.z + A.w) + (B.x + B.y) + (B.z + B.w);
        A = *reinterpret_cast<const float4*>(ssy + base);
        B = *reinterpret_cast<const float4*>(ssy + base + 4);
        ty = (A.x + A.y) + (A.z + A.w) + (B.x + B.y) + (B.z + B.w);
        A = *reinterpret_cast<const float4*>(ssz + base);
        B = *reinterpret_cast<const float4*>(ssz + base + 4);
        tz = (A.x + A.y) + (A.z + A.w) + (B.x + B.y) + (B.z + B.w);
    }

    // warp inclusive scan of thread totals
    float ix = tx, iy = ty, iz = tz;
    #pragma unroll
    for (int o = 1; o < 32; o <<= 1) {
        float ax = __shfl_up_sync(0xFFFFFFFFu, ix, o);
        float ay = __shfl_up_sync(0xFFFFFFFFu, iy, o);
        float az = __shfl_up_sync(0xFFFFFFFFu, iz, o);
        if (lane >= (unsigned)o) { ix += ax; iy += ay; iz += az; }
    }
    if (lane == 31) { wtot[0][warp] = ix; wtot[1][warp] = iy; wtot[2][warp] = iz; }
    __syncthreads();                              // barrier #2

    // ---- all warps redundantly scan the 16 warp totals (no more barriers) ----
    float px = (lane < NWARP) ? wtot[0][lane] : 0.f;
    float py = (lane < NWARP) ? wtot[1][lane] : 0.f;
    float pz = (lane < NWARP) ? wtot[2][lane] : 0.f;
    #pragma unroll
    for (int o = 1; o < NWARP; o <<= 1) {
        float ax = __shfl_up_sync(0xFFFFFFFFu, px, o);
        float ay = __shfl_up_sync(0xFFFFFFFFu, py, o);
        float az = __shfl_up_sync(0xFFFFFFFFu, pz, o);
        if (lane >= (unsigned)o) { px += ax; py += ay; pz += az; }
    }
    const unsigned src = (warp == 0) ? 0u : (warp - 1u);
    float wpx = __shfl_sync(0xFFFFFFFFu, px, src);
    float wpy = __shfl_sync(0xFFFFFFFFu, py, src);
    float wpz = __shfl_sync(0xFFFFFFFFu, pz, src);

    // exclusive offset for this thread's first element
    float offx = dx + (ix - tx) + ((warp == 0) ? 0.f : wpx);
    float offy = dy + (iy - ty) + ((warp == 0) ? 0.f : wpy);
    float offz = dz + (iz - tz) + ((warp == 0) ? 0.f : wpz);

    // ---- Phase B2: re-read smem, running local prefix + abs accumulate ----
    float acc = 0.f;
    if (t == 0) acc = fabsf(dx) + fabsf(dy) + fabsf(dz);   // j=0 (origin)
    {
        float4 XA = *reinterpret_cast<const float4*>(ssx + base);
        float4 XB = *reinterpret_cast<const float4*>(ssx + base + 4);
        float4 YA = *reinterpret_cast<const float4*>(ssy + base);
        float4 YB = *reinterpret_cast<const float4*>(ssy + base + 4);
        float4 ZA = *reinterpret_cast<const float4*>(ssz + base);
        float4 ZB = *reinterpret_cast<const float4*>(ssz + base + 4);
        float xs[EPT] = {XA.x, XA.y, XA.z, XA.w, XB.x, XB.y, XB.z, XB.w};
        float ys[EPT] = {YA.x, YA.y, YA.z, YA.w, YB.x, YB.y, YB.z, YB.w};
        float zs[EPT] = {ZA.x, ZA.y, ZA.z, ZA.w, ZB.x, ZB.y, ZB.z, ZB.w};
        #pragma unroll
        for (int k = 0; k < EPT; k++) {
            offx += xs[k]; offy += ys[k]; offz += zs[k];
            if (base + k < NPTS)
                acc += fabsf(offx) + fabsf(offy) + fabsf(offz);
        }
    }

    // ---- block reduce ----
    #pragma unroll
    for (int o = 16; o > 0; o >>= 1)
        acc += __shfl_down_sync(0xFFFFFFFFu, acc, o);
    if (lane == 0) red[warp] = acc;
    __syncthreads();
    if (warp == 0) {
        float a = (lane < NWARP) ? red[lane] : 0.f;
        #pragma unroll
        for (int o = 16; o > 0; o >>= 1)
            a += __shfl_down_sync(0xFFFFFFFFu, a, o);
        if (lane == 0) g_partial[b] = a * (1.0f / (NPTS + 1));
    }

    // ---- fused deterministic final reduction in the last block ----
    if (t == 0) {
        __threadfence();
        int ticket = atomicAdd(&g_count, 1);
        is_last = (ticket == (int)gridDim.x - 1) ? 1 : 0;
    }
    __syncthreads();
    if (is_last) {
        float a = __ldcg(&g_partial[t])
                + __ldcg(&g_partial[t + TPB])
                + __ldcg(&g_partial[t + 2 * TPB])
                + __ldcg(&g_partial[t + 3 * TPB]);
        #pragma unroll
        for (int o = 16; o > 0; o >>= 1)
            a += __shfl_down_sync(0xFFFFFFFFu, a, o);
        if (lane == 0) red[warp] = a;
        __syncthreads();
        if (warp == 0) {
            float v = (lane < NWARP) ? red[lane] : 0.f;
            #pragma unroll
            for (int o = 16; o > 0; o >>= 1)
                v += __shfl_down_sync(0xFFFFFFFFu, v, o);
            if (lane == 0) {
                out[0] = v;
                atomicExch(&g_count, 0);   // reset for next graph replay
            }
        }
    }
}

extern "C" void kernel_launch(void* const* d_in, const int* in_sizes, int n_in,
                              void* d_out, int out_size)
{
    const float* o3 = (const float*)d_in[0];  // origin_3D        (B,3,1)
    const float* s3 = (const float*)d_in[1];  // spherical_3D     (B,3,N)
    const float* o2 = (const float*)d_in[2];  // origin_2D        (B,3,1)
    const float* s2 = (const float*)d_in[3];  // spherical_2D     (B,3,N)
    const float* df = (const float*)d_in[4];  // deformation_field(B,2,N)
    float* out = (float*)d_out;

    cudaFuncSetAttribute(mpd_fused_kernel,
                         cudaFuncAttributeMaxDynamicSharedMemorySize, SMEM_BYTES);
    mpd_fused_kernel<<<BATCH, TPB, SMEM_BYTES>>>(o3, s3, o2, s2, df, out);
}